// round 14
// baseline (speedup 1.0000x reference)
#include <cuda_runtime.h>
#include <cstdint>

#define VOCAB 100000
#define BATCH 2048
#define SEQ   50
#define HID   256
#define KIN   512

// ---------------- scratch (device globals; no allocation allowed) ----------
__device__ float g_bow_h[BATCH * HID];
__device__ float g_beo_h[BATCH * HID];
// epilogue K-split partials: [side*2+khalf][row][72] (64 embd + 5 pred + pad)
__device__ float g_part[2 * 2 * BATCH * 72];

__device__ __forceinline__ float lky(float v) {
    return (v > 0.f) ? v : 0.2f * v;
}

// ============================================================================
// Fused kernel (champion round-7 structure): blocks [0, K2_BLOCKS) beo GEMM;
// blocks [K2_BLOCKS, +K1_BLOCKS) bow gather. 256 threads.
// Gather setup phases parallelized (syncthreads_and + pair-parallel dedup).
// ============================================================================
#define BM 64
#define BN 64
#define BK 32
#define K2_BLOCKS ((BATCH / BM) * (HID / BN))   // 128
#define K1_ROWS_PER_BLK 2
#define K1_BLOCKS (BATCH / K1_ROWS_PER_BLK)     // 1024

union SmemU {
    struct {                       // GEMM tiles
        float As[BM][BK + 4];
        float Bs[BK][BN];
    } g;
    struct {                       // bow gather scratch
        unsigned int wbuf[K1_ROWS_PER_BLK * SEQ];
        int   toks[K1_ROWS_PER_BLK][SEQ];
        float keep[K1_ROWS_PER_BLK][SEQ];
        float part[K1_ROWS_PER_BLK][HID];
    } b;
};

__global__ __launch_bounds__(256) void fused_hidden_kernel(
    const unsigned int* __restrict__ s_words,
    const float* __restrict__ Wh,    const float* __restrict__ bh,
    const float* __restrict__ X,     const float* __restrict__ W,
    const float* __restrict__ bias)
{
    __shared__ SmemU sm;
    const int tid = threadIdx.x;

    if (blockIdx.x < K2_BLOCKS) {
        // ------------------------- beo GEMM path ---------------------------
        const int bx = blockIdx.x;
        const int m0 = (bx >> 2) * BM;
        const int n0 = (bx & 3) * BN;
        const int tx = tid & 15;
        const int ty = tid >> 4;

        unsigned long long acc[4][2];
        #pragma unroll
        for (int r = 0; r < 4; r++) { acc[r][0] = 0ull; acc[r][1] = 0ull; }

        for (int k0 = 0; k0 < KIN; k0 += BK) {
            #pragma unroll
            for (int f = tid; f < BM * BK / 4; f += 256) {
                int r = f >> 3, q = f & 7;
                *(float4*)&sm.g.As[r][q * 4] =
                    *(const float4*)&X[(m0 + r) * KIN + k0 + q * 4];
            }
            #pragma unroll
            for (int f = tid; f < BK * BN / 4; f += 256) {
                int kr = f >> 4, nq = f & 15;
                *(float4*)&sm.g.Bs[kr][nq * 4] =
                    *(const float4*)&W[(k0 + kr) * HID + n0 + nq * 4];
            }
            __syncthreads();

            #pragma unroll
            for (int k = 0; k < BK; k++) {
                float4 bv = *(const float4*)&sm.g.Bs[k][tx * 4];
                unsigned long long pb0, pb1;
                asm("mov.b64 %0, {%1, %2};" : "=l"(pb0) : "f"(bv.x), "f"(bv.y));
                asm("mov.b64 %0, {%1, %2};" : "=l"(pb1) : "f"(bv.z), "f"(bv.w));
                #pragma unroll
                for (int r = 0; r < 4; r++) {
                    float av = sm.g.As[ty * 4 + r][k];
                    unsigned long long pa;
                    asm("mov.b64 %0, {%1, %1};" : "=l"(pa) : "f"(av));
                    asm("fma.rn.f32x2 %0, %1, %2, %0;" : "+l"(acc[r][0]) : "l"(pa), "l"(pb0));
                    asm("fma.rn.f32x2 %0, %1, %2, %0;" : "+l"(acc[r][1]) : "l"(pa), "l"(pb1));
                }
            }
            __syncthreads();
        }

        const float4 bb = *(const float4*)&bias[n0 + tx * 4];
        #pragma unroll
        for (int r = 0; r < 4; r++) {
            float o0, o1, o2, o3;
            asm("mov.b64 {%0, %1}, %2;" : "=f"(o0), "=f"(o1) : "l"(acc[r][0]));
            asm("mov.b64 {%0, %1}, %2;" : "=f"(o2), "=f"(o3) : "l"(acc[r][1]));
            *(float4*)&g_beo_h[(m0 + ty * 4 + r) * HID + n0 + tx * 4] =
                make_float4(lky(o0 + bb.x), lky(o1 + bb.y),
                            lky(o2 + bb.z), lky(o3 + bb.w));
        }
    } else {
        // ------------------------- bow gather path -------------------------
        const int kb    = blockIdx.x - K2_BLOCKS;
        const int wbase = kb * (K1_ROWS_PER_BLK * SEQ);   // even

        // Phase 1: load 100 words (valid under both dtypes)
        if (tid < K1_ROWS_PER_BLK * SEQ) sm.b.wbuf[tid] = s_words[wbase + tid];

        // Phase 2: parallel dtype detect. Odd local index == odd global index
        // (wbase even); under int64 those words are zero high-halves.
        int pred = 1;
        if (tid < K1_ROWS_PER_BLK * SEQ && (tid & 1)) pred = 0;  // placeholder
        // NOTE: predicate must read wbuf AFTER it is written by this thread;
        // each thread checks only its own word, so no barrier needed first.
        if (tid < K1_ROWS_PER_BLK * SEQ && (tid & 1))
            pred = (sm.b.wbuf[tid] == 0u);
        else
            pred = 1;
        const int is64 = __syncthreads_and(pred);   // barrier + reduction

        // Phase 3: tokens under detected layout; init keep=1
        if (tid < K1_ROWS_PER_BLK * SEQ) {
            int r = tid / SEQ, j = tid - r * SEQ;
            sm.b.toks[r][j] = is64 ? (int)s_words[2 * (wbase + tid)]
                                   : (int)sm.b.wbuf[tid];
            sm.b.keep[r][j] = 1.0f;
        }
        __syncthreads();

        // Phase 4: pair-parallel first-occurrence mask (set semantics).
        // 2 rows x 50x50 pairs = 5000 ids / 256 thr ~= 20 independent iters.
        for (int p = tid; p < K1_ROWS_PER_BLK * SEQ * SEQ; p += 256) {
            int r   = p / (SEQ * SEQ);
            int rem = p - r * (SEQ * SEQ);
            int j1  = rem / SEQ;
            int j2  = rem - j1 * SEQ;
            if (j1 < j2 && sm.b.toks[r][j1] == sm.b.toks[r][j2])
                sm.b.keep[r][j2] = 0.0f;
        }
        __syncthreads();

        // Phase 5: gather, 2 rows x 2 halves x 64 col-threads; 8-deep batches
        const int r    = tid >> 7;
        const int h    = (tid >> 6) & 1;
        const int c4   = (tid & 63) * 4;
        const int jb   = h * (SEQ / 2);       // 25 tokens per half
        const float* __restrict__ Wc = Wh + c4;

        float4 sa[8];
        #pragma unroll
        for (int q = 0; q < 8; q++) sa[q] = make_float4(0.f, 0.f, 0.f, 0.f);

        #pragma unroll
        for (int i = 0; i < 24; i += 8) {
            float4 v[8];
            float  kf[8];
            #pragma unroll
            for (int q = 0; q < 8; q++) {
                v[q]  = *(const float4*)(Wc + sm.b.toks[r][jb + i + q] * HID);
                kf[q] = sm.b.keep[r][jb + i + q];
            }
            #pragma unroll
            for (int q = 0; q < 8; q++) {
                sa[q].x = fmaf(kf[q], v[q].x, sa[q].x);
                sa[q].y = fmaf(kf[q], v[q].y, sa[q].y);
                sa[q].z = fmaf(kf[q], v[q].z, sa[q].z);
                sa[q].w = fmaf(kf[q], v[q].w, sa[q].w);
            }
        }
        {   // tail token (i = 24)
            const float4 v = *(const float4*)(Wc + sm.b.toks[r][jb + 24] * HID);
            const float kf = sm.b.keep[r][jb + 24];
            sa[0].x = fmaf(kf, v.x, sa[0].x); sa[0].y = fmaf(kf, v.y, sa[0].y);
            sa[0].z = fmaf(kf, v.z, sa[0].z); sa[0].w = fmaf(kf, v.w, sa[0].w);
        }

        float4 t;
        t.x = ((sa[0].x + sa[1].x) + (sa[2].x + sa[3].x)) +
              ((sa[4].x + sa[5].x) + (sa[6].x + sa[7].x));
        t.y = ((sa[0].y + sa[1].y) + (sa[2].y + sa[3].y)) +
              ((sa[4].y + sa[5].y) + (sa[6].y + sa[7].y));
        t.z = ((sa[0].z + sa[1].z) + (sa[2].z + sa[3].z)) +
              ((sa[4].z + sa[5].z) + (sa[6].z + sa[7].z));
        t.w = ((sa[0].w + sa[1].w) + (sa[2].w + sa[3].w)) +
              ((sa[4].w + sa[5].w) + (sa[6].w + sa[7].w));

        if (h == 1) *(float4*)&sm.b.part[r][c4] = t;
        __syncthreads();
        if (h == 0) {
            const float4 p  = *(const float4*)&sm.b.part[r][c4];
            const float4 bb = *(const float4*)(bh + c4);
            *(float4*)&g_bow_h[(kb * K1_ROWS_PER_BLK + r) * HID + c4] =
                make_float4(lky(t.x + p.x + bb.x), lky(t.y + p.y + bb.y),
                            lky(t.z + p.z + bb.z), lky(t.w + p.w + bb.w));
        }
    }
}

// ============================================================================
// K-split epilogue (measured 10.7us with combine). grid (128, 2, 2).
// ============================================================================
#define EPB 16
#define HP  20

union EpSmem {
    float WeS[128][64];
    struct {
        float red[4][EPB][64];
        float predred[EPB * 10];
    } r;
};

__global__ __launch_bounds__(256) void epilogue_kernel(
    const float* __restrict__ We_bow, const float* __restrict__ Wp_bow,
    const float* __restrict__ We_beo, const float* __restrict__ Wp_beo)
{
    __shared__ __align__(16) float sh_t[128][HP];
    __shared__ EpSmem u;

    const int side = blockIdx.y;
    const int kh   = blockIdx.z;
    const int row0 = blockIdx.x * EPB;
    const int tid  = threadIdx.x;
    const int kg0  = kh * 128;

    const float* H  = side ? g_beo_h : g_bow_h;
    const float* We = side ? We_beo : We_bow;
    const float* Wp = side ? Wp_beo : Wp_bow;

    #pragma unroll
    for (int f = tid; f < EPB * 32; f += 256) {
        int r = f & 15, cq = f >> 4;
        float4 v = *(const float4*)&H[(row0 + r) * HID + kg0 + cq * 4];
        sh_t[cq * 4 + 0][r] = v.x;
        sh_t[cq * 4 + 1][r] = v.y;
        sh_t[cq * 4 + 2][r] = v.z;
        sh_t[cq * 4 + 3][r] = v.w;
    }
    #pragma unroll
    for (int f = tid; f < 128 * 16; f += 256) {
        int kr = f >> 4, nq = f & 15;
        *(float4*)&u.WeS[kr][nq * 4] =
            *(const float4*)&We[(kg0 + kr) * 64 + nq * 4];
    }
    __syncthreads();

    const int cg = tid & 15;
    const int rg = (tid >> 4) & 3;
    const int kp = tid >> 6;

    unsigned long long acc[4][2];
    #pragma unroll
    for (int r = 0; r < 4; r++) { acc[r][0] = 0ull; acc[r][1] = 0ull; }

    #pragma unroll 8
    for (int k = 0; k < 32; k++) {
        const int kk = kp * 32 + k;
        float4 hv = *(const float4*)&sh_t[kk][rg * 4];
        float4 wv = *(const float4*)&u.WeS[kk][cg * 4];
        unsigned long long pw0, pw1;
        asm("mov.b64 %0, {%1, %2};" : "=l"(pw0) : "f"(wv.x), "f"(wv.y));
        asm("mov.b64 %0, {%1, %2};" : "=l"(pw1) : "f"(wv.z), "f"(wv.w));
        unsigned long long ph0, ph1, ph2, ph3;
        asm("mov.b64 %0, {%1, %1};" : "=l"(ph0) : "f"(hv.x));
        asm("mov.b64 %0, {%1, %1};" : "=l"(ph1) : "f"(hv.y));
        asm("mov.b64 %0, {%1, %1};" : "=l"(ph2) : "f"(hv.z));
        asm("mov.b64 %0, {%1, %1};" : "=l"(ph3) : "f"(hv.w));
        asm("fma.rn.f32x2 %0, %1, %2, %0;" : "+l"(acc[0][0]) : "l"(ph0), "l"(pw0));
        asm("fma.rn.f32x2 %0, %1, %2, %0;" : "+l"(acc[0][1]) : "l"(ph0), "l"(pw1));
        asm("fma.rn.f32x2 %0, %1, %2, %0;" : "+l"(acc[1][0]) : "l"(ph1), "l"(pw0));
        asm("fma.rn.f32x2 %0, %1, %2, %0;" : "+l"(acc[1][1]) : "l"(ph1), "l"(pw1));
        asm("fma.rn.f32x2 %0, %1, %2, %0;" : "+l"(acc[2][0]) : "l"(ph2), "l"(pw0));
        asm("fma.rn.f32x2 %0, %1, %2, %0;" : "+l"(acc[2][1]) : "l"(ph2), "l"(pw1));
        asm("fma.rn.f32x2 %0, %1, %2, %0;" : "+l"(acc[3][0]) : "l"(ph3), "l"(pw0));
        asm("fma.rn.f32x2 %0, %1, %2, %0;" : "+l"(acc[3][1]) : "l"(ph3), "l"(pw1));
    }
    __syncthreads();

    #pragma unroll
    for (int r = 0; r < 4; r++) {
        float a0, a1, a2, a3;
        asm("mov.b64 {%0, %1}, %2;" : "=f"(a0), "=f"(a1) : "l"(acc[r][0]));
        asm("mov.b64 {%0, %1}, %2;" : "=f"(a2), "=f"(a3) : "l"(acc[r][1]));
        *(float4*)&u.r.red[kp][rg * 4 + r][cg * 4] = make_float4(a0, a1, a2, a3);
    }

    if (tid < EPB * 10) {
        int r   = tid / 10;
        int rem = tid - r * 10;
        int j   = rem % 5;
        int kq  = rem / 5;
        const int kb = kq * 64;
        float a0 = 0.f, a1 = 0.f, a2 = 0.f, a3 = 0.f;
        #pragma unroll 4
        for (int k = 0; k < 64; k += 4) {
            a0 = fmaf(sh_t[kb + k + 0][r], Wp[(kg0 + kb + k + 0) * 5 + j], a0);
            a1 = fmaf(sh_t[kb + k + 1][r], Wp[(kg0 + kb + k + 1) * 5 + j], a1);
            a2 = fmaf(sh_t[kb + k + 2][r], Wp[(kg0 + kb + k + 2) * 5 + j], a2);
            a3 = fmaf(sh_t[kb + k + 3][r], Wp[(kg0 + kb + k + 3) * 5 + j], a3);
        }
        u.r.predred[tid] = (a0 + a1) + (a2 + a3);
    }
    __syncthreads();

    float* P = &g_part[((size_t)(side * 2 + kh) * BATCH) * 72];
    {
        const int rr = tid >> 4;
        const int c4 = (tid & 15) * 4;
        float4 p0 = *(const float4*)&u.r.red[0][rr][c4];
        float4 p1 = *(const float4*)&u.r.red[1][rr][c4];
        float4 p2 = *(const float4*)&u.r.red[2][rr][c4];
        float4 p3 = *(const float4*)&u.r.red[3][rr][c4];
        *(float4*)&P[(row0 + rr) * 72 + c4] =
            make_float4((p0.x + p1.x) + (p2.x + p3.x),
                        (p0.y + p1.y) + (p2.y + p3.y),
                        (p0.z + p1.z) + (p2.z + p3.z),
                        (p0.w + p1.w) + (p2.w + p3.w));
    }
    if (tid < EPB * 5) {
        int r = tid / 5, j = tid - r * 5;
        P[(row0 + r) * 72 + 64 + j] =
            u.r.predred[r * 10 + j] + u.r.predred[r * 10 + 5 + j];
    }
}

// ============================================================================
// Combine kernel: out = part[kh=0] + part[kh=1] + bias. grid (552, 2).
// ============================================================================
__global__ __launch_bounds__(256) void combine_kernel(
    const float* __restrict__ be_bow, const float* __restrict__ bp_bow,
    const float* __restrict__ be_beo, const float* __restrict__ bp_beo,
    float* __restrict__ out)
{
    const int side = blockIdx.y;
    const int e    = blockIdx.x * 256 + threadIdx.x;
    if (e >= BATCH * 69) return;

    const float* P0 = &g_part[((size_t)(side * 2 + 0) * BATCH) * 72];
    const float* P1 = &g_part[((size_t)(side * 2 + 1) * BATCH) * 72];

    if (e < BATCH * 64) {
        int row = e >> 6, c = e & 63;
        float b = side ? be_beo[c] : be_bow[c];
        out[(side ? BATCH * 64 : 0) + e] =
            P0[row * 72 + c] + P1[row * 72 + c] + b;
    } else {
        int e2 = e - BATCH * 64;
        int row = e2 / 5, j = e2 - row * 5;
        float b = side ? bp_beo[j] : bp_bow[j];
        out[BATCH * 128 + side * BATCH * 5 + e2] =
            P0[row * 72 + 64 + j] + P1[row * 72 + 64 + j] + b;
    }
}

// ============================================================================
extern "C" void kernel_launch(void* const* d_in, const int* in_sizes, int n_in,
                              void* d_out, int out_size)
{
    const unsigned int* s_words = (const unsigned int*)d_in[0];
    const float* x        = (const float*)d_in[1];
    const float* W_bow_h  = (const float*)d_in[2];
    const float* b_bow_h  = (const float*)d_in[3];
    const float* W_bow_p  = (const float*)d_in[4];
    const float* b_bow_p  = (const float*)d_in[5];
    const float* W_bow_e  = (const float*)d_in[6];
    const float* b_bow_e  = (const float*)d_in[7];
    const float* W_beo_h  = (const float*)d_in[8];
    const float* b_beo_h  = (const float*)d_in[9];
    const float* W_beo_p  = (const float*)d_in[10];
    const float* b_beo_p  = (const float*)d_in[11];
    const float* W_beo_e  = (const float*)d_in[12];
    const float* b_beo_e  = (const float*)d_in[13];
    float* out = (float*)d_out;

    fused_hidden_kernel<<<K2_BLOCKS + K1_BLOCKS, 256>>>(
        s_words, W_bow_h, b_bow_h, x, W_beo_h, b_beo_h);

    dim3 g3(BATCH / EPB, 2, 2);
    epilogue_kernel<<<g3, 256>>>(W_bow_e, W_bow_p, W_beo_e, W_beo_p);

    dim3 g4((BATCH * 69 + 255) / 256, 2);
    combine_kernel<<<g4, 256>>>(b_bow_e, b_bow_p, b_beo_e, b_beo_p, out);
}

// round 15
// speedup vs baseline: 1.0036x; 1.0036x over previous
#include <cuda_runtime.h>
#include <cstdint>

#define VOCAB 100000
#define BATCH 2048
#define SEQ   50
#define HID   256
#define KIN   512

// ---------------- scratch (device globals; no allocation allowed) ----------
__device__ float g_bow_h[BATCH * HID];
__device__ float g_beo_h[BATCH * HID];

__device__ __forceinline__ float lky(float v) {
    return (v > 0.f) ? v : 0.2f * v;
}

// ============================================================================
// Fused kernel: blocks [0, K2_BLOCKS) beo GEMM; blocks [K2_BLOCKS, +K1_BLOCKS)
// bow gather. 256 threads. launch_bounds(256,4): 64-reg cap -> 4 blocks/SM.
// Gather keeps 8-deep load batches but only 4 rotating accumulators.
// ============================================================================
#define BM 64
#define BN 64
#define BK 32
#define K2_BLOCKS ((BATCH / BM) * (HID / BN))   // 128
#define K1_ROWS_PER_BLK 2
#define K1_BLOCKS (BATCH / K1_ROWS_PER_BLK)     // 1024

union SmemU {
    struct {                       // GEMM tiles
        float As[BM][BK + 4];
        float Bs[BK][BN];
    } g;
    struct {                       // bow gather scratch
        unsigned int wbuf[K1_ROWS_PER_BLK * SEQ];
        int   toks[K1_ROWS_PER_BLK][SEQ];
        float keep[K1_ROWS_PER_BLK][SEQ];
        float part[K1_ROWS_PER_BLK][HID];
    } b;
};

__global__ __launch_bounds__(256, 4) void fused_hidden_kernel(
    const unsigned int* __restrict__ s_words,
    const float* __restrict__ Wh,    const float* __restrict__ bh,
    const float* __restrict__ X,     const float* __restrict__ W,
    const float* __restrict__ bias)
{
    __shared__ SmemU sm;
    const int tid = threadIdx.x;

    if (blockIdx.x < K2_BLOCKS) {
        // ------------------------- beo GEMM path ---------------------------
        const int bx = blockIdx.x;
        const int m0 = (bx >> 2) * BM;
        const int n0 = (bx & 3) * BN;
        const int tx = tid & 15;
        const int ty = tid >> 4;

        unsigned long long acc[4][2];
        #pragma unroll
        for (int r = 0; r < 4; r++) { acc[r][0] = 0ull; acc[r][1] = 0ull; }

        for (int k0 = 0; k0 < KIN; k0 += BK) {
            #pragma unroll
            for (int f = tid; f < BM * BK / 4; f += 256) {
                int r = f >> 3, q = f & 7;
                *(float4*)&sm.g.As[r][q * 4] =
                    *(const float4*)&X[(m0 + r) * KIN + k0 + q * 4];
            }
            #pragma unroll
            for (int f = tid; f < BK * BN / 4; f += 256) {
                int kr = f >> 4, nq = f & 15;
                *(float4*)&sm.g.Bs[kr][nq * 4] =
                    *(const float4*)&W[(k0 + kr) * HID + n0 + nq * 4];
            }
            __syncthreads();

            #pragma unroll
            for (int k = 0; k < BK; k++) {
                float4 bv = *(const float4*)&sm.g.Bs[k][tx * 4];
                unsigned long long pb0, pb1;
                asm("mov.b64 %0, {%1, %2};" : "=l"(pb0) : "f"(bv.x), "f"(bv.y));
                asm("mov.b64 %0, {%1, %2};" : "=l"(pb1) : "f"(bv.z), "f"(bv.w));
                #pragma unroll
                for (int r = 0; r < 4; r++) {
                    float av = sm.g.As[ty * 4 + r][k];
                    unsigned long long pa;
                    asm("mov.b64 %0, {%1, %1};" : "=l"(pa) : "f"(av));
                    asm("fma.rn.f32x2 %0, %1, %2, %0;" : "+l"(acc[r][0]) : "l"(pa), "l"(pb0));
                    asm("fma.rn.f32x2 %0, %1, %2, %0;" : "+l"(acc[r][1]) : "l"(pa), "l"(pb1));
                }
            }
            __syncthreads();
        }

        const float4 bb = *(const float4*)&bias[n0 + tx * 4];
        #pragma unroll
        for (int r = 0; r < 4; r++) {
            float o0, o1, o2, o3;
            asm("mov.b64 {%0, %1}, %2;" : "=f"(o0), "=f"(o1) : "l"(acc[r][0]));
            asm("mov.b64 {%0, %1}, %2;" : "=f"(o2), "=f"(o3) : "l"(acc[r][1]));
            *(float4*)&g_beo_h[(m0 + ty * 4 + r) * HID + n0 + tx * 4] =
                make_float4(lky(o0 + bb.x), lky(o1 + bb.y),
                            lky(o2 + bb.z), lky(o3 + bb.w));
        }
    } else {
        // ------------------------- bow gather path -------------------------
        const int kb    = blockIdx.x - K2_BLOCKS;
        const int wbase = kb * (K1_ROWS_PER_BLK * SEQ);   // even

        // Phase 1: load 100 words (valid under both dtypes)
        if (tid < K1_ROWS_PER_BLK * SEQ) sm.b.wbuf[tid] = s_words[wbase + tid];

        // Phase 2: parallel dtype detect via syncthreads_and (odd local index
        // == odd global index since wbase is even; int64 => zero high-halves).
        int pred = 1;
        if (tid < K1_ROWS_PER_BLK * SEQ && (tid & 1))
            pred = (sm.b.wbuf[tid] == 0u);
        const int is64 = __syncthreads_and(pred);

        // Phase 3: tokens under detected layout
        if (tid < K1_ROWS_PER_BLK * SEQ) {
            int r = tid / SEQ, j = tid - r * SEQ;
            sm.b.toks[r][j] = is64 ? (int)s_words[2 * (wbase + tid)]
                                   : (int)sm.b.wbuf[tid];
        }
        __syncthreads();

        // Phase 4: first-occurrence keep mask (set semantics)
        if (tid < K1_ROWS_PER_BLK * SEQ) {
            int r = tid / SEQ, j = tid - r * SEQ;
            int t = sm.b.toks[r][j];
            float k = 1.0f;
            for (int j2 = 0; j2 < j; j2++)
                if (sm.b.toks[r][j2] == t) { k = 0.0f; break; }
            sm.b.keep[r][j] = k;
        }
        __syncthreads();

        // Phase 5: gather, 2 rows x 2 halves x 64 col-threads;
        // 8-deep load batches feeding 4 rotating accumulators.
        const int r    = tid >> 7;
        const int h    = (tid >> 6) & 1;
        const int c4   = (tid & 63) * 4;
        const int jb   = h * (SEQ / 2);       // 25 tokens per half
        const float* __restrict__ Wc = Wh + c4;

        float4 sa[4];
        #pragma unroll
        for (int q = 0; q < 4; q++) sa[q] = make_float4(0.f, 0.f, 0.f, 0.f);

        #pragma unroll
        for (int i = 0; i < 24; i += 8) {
            float4 v[8];
            float  kf[8];
            #pragma unroll
            for (int q = 0; q < 8; q++) {
                v[q]  = *(const float4*)(Wc + sm.b.toks[r][jb + i + q] * HID);
                kf[q] = sm.b.keep[r][jb + i + q];
            }
            #pragma unroll
            for (int q = 0; q < 8; q++) {
                float4& a = sa[q & 3];
                a.x = fmaf(kf[q], v[q].x, a.x);
                a.y = fmaf(kf[q], v[q].y, a.y);
                a.z = fmaf(kf[q], v[q].z, a.z);
                a.w = fmaf(kf[q], v[q].w, a.w);
            }
        }
        {   // tail token (i = 24)
            const float4 v = *(const float4*)(Wc + sm.b.toks[r][jb + 24] * HID);
            const float kf = sm.b.keep[r][jb + 24];
            sa[0].x = fmaf(kf, v.x, sa[0].x); sa[0].y = fmaf(kf, v.y, sa[0].y);
            sa[0].z = fmaf(kf, v.z, sa[0].z); sa[0].w = fmaf(kf, v.w, sa[0].w);
        }

        float4 t;
        t.x = (sa[0].x + sa[1].x) + (sa[2].x + sa[3].x);
        t.y = (sa[0].y + sa[1].y) + (sa[2].y + sa[3].y);
        t.z = (sa[0].z + sa[1].z) + (sa[2].z + sa[3].z);
        t.w = (sa[0].w + sa[1].w) + (sa[2].w + sa[3].w);

        if (h == 1) *(float4*)&sm.b.part[r][c4] = t;
        __syncthreads();
        if (h == 0) {
            const float4 p  = *(const float4*)&sm.b.part[r][c4];
            const float4 bb = *(const float4*)(bh + c4);
            *(float4*)&g_bow_h[(kb * K1_ROWS_PER_BLK + r) * HID + c4] =
                make_float4(lky(t.x + p.x + bb.x), lky(t.y + p.y + bb.y),
                            lky(t.z + p.z + bb.z), lky(t.w + p.w + bb.w));
        }
    }
}

// ============================================================================
// K3 v4 epilogue (round-7 champion config). EPB=16, grid (128, 2).
//   - H staged TRANSPOSED: sh_t[k][row]
//   - We staged in 2 chunks of 128 k (32 KB)
//   - thread tile 4 rows x 4 cols x K-split-4
// ============================================================================
#define EPB 16
#define HP  20                                  // padded row stride (floats)

union EpSmem {
    float WeS[128][64];                         // 32 KB weight stage
    struct {
        float red[4][EPB][64];                  // 16 KB embd K-partials
        float predred[EPB * 10];                // pred K-partials
    } r;
};

__global__ __launch_bounds__(256) void epilogue_kernel(
    const float* __restrict__ We_bow, const float* __restrict__ be_bow,
    const float* __restrict__ Wp_bow, const float* __restrict__ bp_bow,
    const float* __restrict__ We_beo, const float* __restrict__ be_beo,
    const float* __restrict__ Wp_beo, const float* __restrict__ bp_beo,
    float* __restrict__ out)
{
    __shared__ __align__(16) float sh_t[HID][HP];   // 20 KB transposed H
    __shared__ EpSmem u;

    const int side = blockIdx.y;
    const int row0 = blockIdx.x * EPB;
    const int tid  = threadIdx.x;

    const float* H  = side ? g_beo_h : g_bow_h;
    const float* We = side ? We_beo : We_bow;
    const float* be = side ? be_beo : be_bow;
    const float* Wp = side ? Wp_beo : Wp_bow;
    const float* bp = side ? bp_beo : bp_bow;

    // stage H transposed: 1024 float4
    #pragma unroll
    for (int f = tid; f < EPB * (HID / 4); f += 256) {
        int r = f & 15, cq = f >> 4;
        float4 v = *(const float4*)&H[(row0 + r) * HID + cq * 4];
        sh_t[cq * 4 + 0][r] = v.x;
        sh_t[cq * 4 + 1][r] = v.y;
        sh_t[cq * 4 + 2][r] = v.z;
        sh_t[cq * 4 + 3][r] = v.w;
    }

    const int cg = tid & 15;           // 16 col groups * 4 cols
    const int rg = (tid >> 4) & 3;     // 4 row groups * 4 rows
    const int kp = tid >> 6;           // 4 K partitions (32 k per chunk each)

    unsigned long long acc[4][2];
    #pragma unroll
    for (int r = 0; r < 4; r++) { acc[r][0] = 0ull; acc[r][1] = 0ull; }

    #pragma unroll
    for (int kc = 0; kc < 2; kc++) {
        // stage We rows [kc*128, +128): 2048 float4 / 256 thr = 8 each
        #pragma unroll
        for (int f = tid; f < 128 * 16; f += 256) {
            int kr = f >> 4, nq = f & 15;
            *(float4*)&u.WeS[kr][nq * 4] =
                *(const float4*)&We[(kc * 128 + kr) * 64 + nq * 4];
        }
        __syncthreads();

        #pragma unroll 8
        for (int k = 0; k < 32; k++) {
            const int kk = kp * 32 + k;            // row within WeS chunk
            const int kg = kc * 128 + kk;          // global k
            float4 hv = *(const float4*)&sh_t[kg][rg * 4];
            float4 wv = *(const float4*)&u.WeS[kk][cg * 4];
            unsigned long long pw0, pw1;
            asm("mov.b64 %0, {%1, %2};" : "=l"(pw0) : "f"(wv.x), "f"(wv.y));
            asm("mov.b64 %0, {%1, %2};" : "=l"(pw1) : "f"(wv.z), "f"(wv.w));
            unsigned long long ph0, ph1, ph2, ph3;
            asm("mov.b64 %0, {%1, %1};" : "=l"(ph0) : "f"(hv.x));
            asm("mov.b64 %0, {%1, %1};" : "=l"(ph1) : "f"(hv.y));
            asm("mov.b64 %0, {%1, %1};" : "=l"(ph2) : "f"(hv.z));
            asm("mov.b64 %0, {%1, %1};" : "=l"(ph3) : "f"(hv.w));
            asm("fma.rn.f32x2 %0, %1, %2, %0;" : "+l"(acc[0][0]) : "l"(ph0), "l"(pw0));
            asm("fma.rn.f32x2 %0, %1, %2, %0;" : "+l"(acc[0][1]) : "l"(ph0), "l"(pw1));
            asm("fma.rn.f32x2 %0, %1, %2, %0;" : "+l"(acc[1][0]) : "l"(ph1), "l"(pw0));
            asm("fma.rn.f32x2 %0, %1, %2, %0;" : "+l"(acc[1][1]) : "l"(ph1), "l"(pw1));
            asm("fma.rn.f32x2 %0, %1, %2, %0;" : "+l"(acc[2][0]) : "l"(ph2), "l"(pw0));
            asm("fma.rn.f32x2 %0, %1, %2, %0;" : "+l"(acc[2][1]) : "l"(ph2), "l"(pw1));
            asm("fma.rn.f32x2 %0, %1, %2, %0;" : "+l"(acc[3][0]) : "l"(ph3), "l"(pw0));
            asm("fma.rn.f32x2 %0, %1, %2, %0;" : "+l"(acc[3][1]) : "l"(ph3), "l"(pw1));
        }
        __syncthreads();   // done with this WeS chunk
    }

    // ---- store embd K-partials (union now safe to reuse) ----
    #pragma unroll
    for (int r = 0; r < 4; r++) {
        float a0, a1, a2, a3;
        asm("mov.b64 {%0, %1}, %2;" : "=f"(a0), "=f"(a1) : "l"(acc[r][0]));
        asm("mov.b64 {%0, %1}, %2;" : "=f"(a2), "=f"(a3) : "l"(acc[r][1]));
        *(float4*)&u.r.red[kp][rg * 4 + r][cg * 4] = make_float4(a0, a1, a2, a3);
    }

    // ---- pred K-partials: 160 threads, 4 independent chains each ----
    if (tid < EPB * 10) {
        int r   = tid / 10;
        int rem = tid - r * 10;
        int j   = rem % 5;
        int kq  = rem / 5;
        const int kb = kq * 128;
        float a0 = 0.f, a1 = 0.f, a2 = 0.f, a3 = 0.f;
        #pragma unroll 4
        for (int k = 0; k < 128; k += 4) {
            a0 = fmaf(sh_t[kb + k + 0][r], Wp[(kb + k + 0) * 5 + j], a0);
            a1 = fmaf(sh_t[kb + k + 1][r], Wp[(kb + k + 1) * 5 + j], a1);
            a2 = fmaf(sh_t[kb + k + 2][r], Wp[(kb + k + 2) * 5 + j], a2);
            a3 = fmaf(sh_t[kb + k + 3][r], Wp[(kb + k + 3) * 5 + j], a3);
        }
        u.r.predred[tid] = (a0 + a1) + (a2 + a3);
    }
    __syncthreads();

    // ---- final combine + store ----
    {
        const int rr = tid >> 4;
        const int c4 = (tid & 15) * 4;
        float4 p0 = *(const float4*)&u.r.red[0][rr][c4];
        float4 p1 = *(const float4*)&u.r.red[1][rr][c4];
        float4 p2 = *(const float4*)&u.r.red[2][rr][c4];
        float4 p3 = *(const float4*)&u.r.red[3][rr][c4];
        float4 bbv = *(const float4*)&be[c4];
        const int ebase = side ? (BATCH * 64) : 0;
        *(float4*)&out[ebase + (row0 + rr) * 64 + c4] =
            make_float4((p0.x + p1.x) + (p2.x + p3.x) + bbv.x,
                        (p0.y + p1.y) + (p2.y + p3.y) + bbv.y,
                        (p0.z + p1.z) + (p2.z + p3.z) + bbv.z,
                        (p0.w + p1.w) + (p2.w + p3.w) + bbv.w);
    }
    if (tid < EPB * 5) {
        int r = tid / 5, j = tid - r * 5;
        float v = u.r.predred[r * 10 + j] + u.r.predred[r * 10 + 5 + j] + bp[j];
        const int pbase = BATCH * 128 + (side ? BATCH * 5 : 0);
        out[pbase + (row0 + r) * 5 + j] = v;
    }
}

// ============================================================================
extern "C" void kernel_launch(void* const* d_in, const int* in_sizes, int n_in,
                              void* d_out, int out_size)
{
    const unsigned int* s_words = (const unsigned int*)d_in[0];
    const float* x        = (const float*)d_in[1];
    const float* W_bow_h  = (const float*)d_in[2];
    const float* b_bow_h  = (const float*)d_in[3];
    const float* W_bow_p  = (const float*)d_in[4];
    const float* b_bow_p  = (const float*)d_in[5];
    const float* W_bow_e  = (const float*)d_in[6];
    const float* b_bow_e  = (const float*)d_in[7];
    const float* W_beo_h  = (const float*)d_in[8];
    const float* b_beo_h  = (const float*)d_in[9];
    const float* W_beo_p  = (const float*)d_in[10];
    const float* b_beo_p  = (const float*)d_in[11];
    const float* W_beo_e  = (const float*)d_in[12];
    const float* b_beo_e  = (const float*)d_in[13];
    float* out = (float*)d_out;

    fused_hidden_kernel<<<K2_BLOCKS + K1_BLOCKS, 256>>>(
        s_words, W_bow_h, b_bow_h, x, W_beo_h, b_beo_h);

    dim3 g3(BATCH / EPB, 2);
    epilogue_kernel<<<g3, 256>>>(W_bow_e, b_bow_e, W_bow_p, b_bow_p,
                                 W_beo_e, b_beo_e, W_beo_p, b_beo_p, out);
}

// round 16
// speedup vs baseline: 1.0426x; 1.0388x over previous
#include <cuda_runtime.h>
#include <cstdint>

#define VOCAB 100000
#define BATCH 2048
#define SEQ   50
#define HID   256
#define KIN   512

// ---------------- scratch (device globals; no allocation allowed) ----------
__device__ float g_bow_h[BATCH * HID];
__device__ float g_beo_h[BATCH * HID];

__device__ __forceinline__ float lky(float v) {
    return (v > 0.f) ? v : 0.2f * v;
}

// ============================================================================
// Fused kernel (VERBATIM round 7 — measured best, do not touch):
// blocks [0, K2_BLOCKS) beo GEMM; blocks [K2_BLOCKS, +K1_BLOCKS) bow gather.
// ============================================================================
#define BM 64
#define BN 64
#define BK 32
#define K2_BLOCKS ((BATCH / BM) * (HID / BN))   // 128
#define K1_ROWS_PER_BLK 2
#define K1_BLOCKS (BATCH / K1_ROWS_PER_BLK)     // 1024

union SmemU {
    struct {                       // GEMM tiles
        float As[BM][BK + 4];
        float Bs[BK][BN];
    } g;
    struct {                       // bow gather scratch
        unsigned int wbuf[K1_ROWS_PER_BLK * SEQ];
        int   toks[K1_ROWS_PER_BLK][SEQ];
        float keep[K1_ROWS_PER_BLK][SEQ];
        float part[K1_ROWS_PER_BLK][HID];
        int   is64;
    } b;
};

__global__ __launch_bounds__(256) void fused_hidden_kernel(
    const unsigned int* __restrict__ s_words,
    const float* __restrict__ Wh,    const float* __restrict__ bh,
    const float* __restrict__ X,     const float* __restrict__ W,
    const float* __restrict__ bias)
{
    __shared__ SmemU sm;
    const int tid = threadIdx.x;

    if (blockIdx.x < K2_BLOCKS) {
        // ------------------------- beo GEMM path ---------------------------
        const int bx = blockIdx.x;
        const int m0 = (bx >> 2) * BM;
        const int n0 = (bx & 3) * BN;
        const int tx = tid & 15;
        const int ty = tid >> 4;

        unsigned long long acc[4][2];
        #pragma unroll
        for (int r = 0; r < 4; r++) { acc[r][0] = 0ull; acc[r][1] = 0ull; }

        for (int k0 = 0; k0 < KIN; k0 += BK) {
            #pragma unroll
            for (int f = tid; f < BM * BK / 4; f += 256) {
                int r = f >> 3, q = f & 7;
                *(float4*)&sm.g.As[r][q * 4] =
                    *(const float4*)&X[(m0 + r) * KIN + k0 + q * 4];
            }
            #pragma unroll
            for (int f = tid; f < BK * BN / 4; f += 256) {
                int kr = f >> 4, nq = f & 15;
                *(float4*)&sm.g.Bs[kr][nq * 4] =
                    *(const float4*)&W[(k0 + kr) * HID + n0 + nq * 4];
            }
            __syncthreads();

            #pragma unroll
            for (int k = 0; k < BK; k++) {
                float4 bv = *(const float4*)&sm.g.Bs[k][tx * 4];
                unsigned long long pb0, pb1;
                asm("mov.b64 %0, {%1, %2};" : "=l"(pb0) : "f"(bv.x), "f"(bv.y));
                asm("mov.b64 %0, {%1, %2};" : "=l"(pb1) : "f"(bv.z), "f"(bv.w));
                #pragma unroll
                for (int r = 0; r < 4; r++) {
                    float av = sm.g.As[ty * 4 + r][k];
                    unsigned long long pa;
                    asm("mov.b64 %0, {%1, %1};" : "=l"(pa) : "f"(av));
                    asm("fma.rn.f32x2 %0, %1, %2, %0;" : "+l"(acc[r][0]) : "l"(pa), "l"(pb0));
                    asm("fma.rn.f32x2 %0, %1, %2, %0;" : "+l"(acc[r][1]) : "l"(pa), "l"(pb1));
                }
            }
            __syncthreads();
        }

        const float4 bb = *(const float4*)&bias[n0 + tx * 4];
        #pragma unroll
        for (int r = 0; r < 4; r++) {
            float o0, o1, o2, o3;
            asm("mov.b64 {%0, %1}, %2;" : "=f"(o0), "=f"(o1) : "l"(acc[r][0]));
            asm("mov.b64 {%0, %1}, %2;" : "=f"(o2), "=f"(o3) : "l"(acc[r][1]));
            *(float4*)&g_beo_h[(m0 + ty * 4 + r) * HID + n0 + tx * 4] =
                make_float4(lky(o0 + bb.x), lky(o1 + bb.y),
                            lky(o2 + bb.z), lky(o3 + bb.w));
        }
    } else {
        // ------------------------- bow gather path -------------------------
        const int kb    = blockIdx.x - K2_BLOCKS;
        const int wbase = kb * (K1_ROWS_PER_BLK * SEQ);

        if (tid < K1_ROWS_PER_BLK * SEQ) sm.b.wbuf[tid] = s_words[wbase + tid];
        __syncthreads();

        if (tid == 0) {
            int all0 = 1;
            #pragma unroll
            for (int i = 1; i < K1_ROWS_PER_BLK * SEQ; i += 2)
                all0 &= (sm.b.wbuf[i] == 0u);
            sm.b.is64 = all0;
        }
        __syncthreads();

        const int is64 = sm.b.is64;
        if (tid < K1_ROWS_PER_BLK * SEQ) {
            int r = tid / SEQ, j = tid - r * SEQ;
            sm.b.toks[r][j] = is64 ? (int)s_words[2 * (wbase + tid)]
                                   : (int)sm.b.wbuf[tid];
        }
        __syncthreads();

        if (tid < K1_ROWS_PER_BLK * SEQ) {
            int r = tid / SEQ, j = tid - r * SEQ;
            int t = sm.b.toks[r][j];
            float k = 1.0f;
            for (int j2 = 0; j2 < j; j2++)
                if (sm.b.toks[r][j2] == t) { k = 0.0f; break; }
            sm.b.keep[r][j] = k;
        }
        __syncthreads();

        // gather: 2 rows x 2 halves x 64 col-threads; 8-deep load batches
        const int r    = tid >> 7;
        const int h    = (tid >> 6) & 1;
        const int c4   = (tid & 63) * 4;
        const int jb   = h * (SEQ / 2);       // 25 tokens per half
        const float* __restrict__ Wc = Wh + c4;

        float4 sa[8];
        #pragma unroll
        for (int q = 0; q < 8; q++) sa[q] = make_float4(0.f, 0.f, 0.f, 0.f);

        #pragma unroll
        for (int i = 0; i < 24; i += 8) {
            float4 v[8];
            float  kf[8];
            #pragma unroll
            for (int q = 0; q < 8; q++) {
                v[q]  = *(const float4*)(Wc + sm.b.toks[r][jb + i + q] * HID);
                kf[q] = sm.b.keep[r][jb + i + q];
            }
            #pragma unroll
            for (int q = 0; q < 8; q++) {
                sa[q].x = fmaf(kf[q], v[q].x, sa[q].x);
                sa[q].y = fmaf(kf[q], v[q].y, sa[q].y);
                sa[q].z = fmaf(kf[q], v[q].z, sa[q].z);
                sa[q].w = fmaf(kf[q], v[q].w, sa[q].w);
            }
        }
        {   // tail token (i = 24)
            const float4 v = *(const float4*)(Wc + sm.b.toks[r][jb + 24] * HID);
            const float kf = sm.b.keep[r][jb + 24];
            sa[0].x = fmaf(kf, v.x, sa[0].x); sa[0].y = fmaf(kf, v.y, sa[0].y);
            sa[0].z = fmaf(kf, v.z, sa[0].z); sa[0].w = fmaf(kf, v.w, sa[0].w);
        }

        float4 t;
        t.x = ((sa[0].x + sa[1].x) + (sa[2].x + sa[3].x)) +
              ((sa[4].x + sa[5].x) + (sa[6].x + sa[7].x));
        t.y = ((sa[0].y + sa[1].y) + (sa[2].y + sa[3].y)) +
              ((sa[4].y + sa[5].y) + (sa[6].y + sa[7].y));
        t.z = ((sa[0].z + sa[1].z) + (sa[2].z + sa[3].z)) +
              ((sa[4].z + sa[5].z) + (sa[6].z + sa[7].z));
        t.w = ((sa[0].w + sa[1].w) + (sa[2].w + sa[3].w)) +
              ((sa[4].w + sa[5].w) + (sa[6].w + sa[7].w));

        if (h == 1) *(float4*)&sm.b.part[r][c4] = t;
        __syncthreads();
        if (h == 0) {
            const float4 p  = *(const float4*)&sm.b.part[r][c4];
            const float4 bb = *(const float4*)(bh + c4);
            *(float4*)&g_bow_h[(kb * K1_ROWS_PER_BLK + r) * HID + c4] =
                make_float4(lky(t.x + p.x + bb.x), lky(t.y + p.y + bb.y),
                            lky(t.z + p.z + bb.z), lky(t.w + p.w + bb.w));
        }
    }
}

// ============================================================================
// K3 v7: epilogue, 512 THREADS per block (same traffic as v4, 2x warps).
// EPB=16, grid (128, 2). K split 8-ways inside the block.
// ============================================================================
#define EPB 16
#define HP  20                                  // padded row stride (floats)

union EpSmem {
    float WeS[128][64];                         // 32 KB weight stage
    struct {
        float red[8][EPB][64];                  // 32 KB embd K-partials
        float predred[EPB * 10];                // pred K-partials
    } r;
};

__global__ __launch_bounds__(512) void epilogue_kernel(
    const float* __restrict__ We_bow, const float* __restrict__ be_bow,
    const float* __restrict__ Wp_bow, const float* __restrict__ bp_bow,
    const float* __restrict__ We_beo, const float* __restrict__ be_beo,
    const float* __restrict__ Wp_beo, const float* __restrict__ bp_beo,
    float* __restrict__ out)
{
    __shared__ __align__(16) float sh_t[HID][HP];   // 20 KB transposed H
    __shared__ EpSmem u;

    const int side = blockIdx.y;
    const int row0 = blockIdx.x * EPB;
    const int tid  = threadIdx.x;

    const float* H  = side ? g_beo_h : g_bow_h;
    const float* We = side ? We_beo : We_bow;
    const float* be = side ? be_beo : be_bow;
    const float* Wp = side ? Wp_beo : Wp_bow;
    const float* bp = side ? bp_beo : bp_bow;

    // stage H transposed: 1024 float4 / 512 thr = 2 each
    #pragma unroll
    for (int f = tid; f < EPB * (HID / 4); f += 512) {
        int r = f & 15, cq = f >> 4;
        float4 v = *(const float4*)&H[(row0 + r) * HID + cq * 4];
        sh_t[cq * 4 + 0][r] = v.x;
        sh_t[cq * 4 + 1][r] = v.y;
        sh_t[cq * 4 + 2][r] = v.z;
        sh_t[cq * 4 + 3][r] = v.w;
    }

    const int cg = tid & 15;           // 16 col groups * 4 cols
    const int rg = (tid >> 4) & 3;     // 4 row groups * 4 rows
    const int kp = tid >> 6;           // 8 K partitions (16 k per chunk each)

    unsigned long long acc[4][2];
    #pragma unroll
    for (int r = 0; r < 4; r++) { acc[r][0] = 0ull; acc[r][1] = 0ull; }

    #pragma unroll
    for (int kc = 0; kc < 2; kc++) {
        // stage We rows [kc*128, +128): 2048 float4 / 512 thr = 4 each
        #pragma unroll
        for (int f = tid; f < 128 * 16; f += 512) {
            int kr = f >> 4, nq = f & 15;
            *(float4*)&u.WeS[kr][nq * 4] =
                *(const float4*)&We[(kc * 128 + kr) * 64 + nq * 4];
        }
        __syncthreads();

        #pragma unroll 8
        for (int k = 0; k < 16; k++) {
            const int kk = kp * 16 + k;            // row within WeS chunk
            const int kg = kc * 128 + kk;          // global k
            float4 hv = *(const float4*)&sh_t[kg][rg * 4];
            float4 wv = *(const float4*)&u.WeS[kk][cg * 4];
            unsigned long long pw0, pw1;
            asm("mov.b64 %0, {%1, %2};" : "=l"(pw0) : "f"(wv.x), "f"(wv.y));
            asm("mov.b64 %0, {%1, %2};" : "=l"(pw1) : "f"(wv.z), "f"(wv.w));
            unsigned long long ph0, ph1, ph2, ph3;
            asm("mov.b64 %0, {%1, %1};" : "=l"(ph0) : "f"(hv.x));
            asm("mov.b64 %0, {%1, %1};" : "=l"(ph1) : "f"(hv.y));
            asm("mov.b64 %0, {%1, %1};" : "=l"(ph2) : "f"(hv.z));
            asm("mov.b64 %0, {%1, %1};" : "=l"(ph3) : "f"(hv.w));
            asm("fma.rn.f32x2 %0, %1, %2, %0;" : "+l"(acc[0][0]) : "l"(ph0), "l"(pw0));
            asm("fma.rn.f32x2 %0, %1, %2, %0;" : "+l"(acc[0][1]) : "l"(ph0), "l"(pw1));
            asm("fma.rn.f32x2 %0, %1, %2, %0;" : "+l"(acc[1][0]) : "l"(ph1), "l"(pw0));
            asm("fma.rn.f32x2 %0, %1, %2, %0;" : "+l"(acc[1][1]) : "l"(ph1), "l"(pw1));
            asm("fma.rn.f32x2 %0, %1, %2, %0;" : "+l"(acc[2][0]) : "l"(ph2), "l"(pw0));
            asm("fma.rn.f32x2 %0, %1, %2, %0;" : "+l"(acc[2][1]) : "l"(ph2), "l"(pw1));
            asm("fma.rn.f32x2 %0, %1, %2, %0;" : "+l"(acc[3][0]) : "l"(ph3), "l"(pw0));
            asm("fma.rn.f32x2 %0, %1, %2, %0;" : "+l"(acc[3][1]) : "l"(ph3), "l"(pw1));
        }
        __syncthreads();   // done with this WeS chunk
    }

    // ---- store embd kp-partials (union now safe to reuse) ----
    #pragma unroll
    for (int r = 0; r < 4; r++) {
        float a0, a1, a2, a3;
        asm("mov.b64 {%0, %1}, %2;" : "=f"(a0), "=f"(a1) : "l"(acc[r][0]));
        asm("mov.b64 {%0, %1}, %2;" : "=f"(a2), "=f"(a3) : "l"(acc[r][1]));
        *(float4*)&u.r.red[kp][rg * 4 + r][cg * 4] = make_float4(a0, a1, a2, a3);
    }

    // ---- pred K-partials: 160 threads, 4 independent chains each ----
    if (tid < EPB * 10) {
        int r   = tid / 10;
        int rem = tid - r * 10;
        int j   = rem % 5;
        int kq  = rem / 5;
        const int kb = kq * 128;
        float a0 = 0.f, a1 = 0.f, a2 = 0.f, a3 = 0.f;
        #pragma unroll 4
        for (int k = 0; k < 128; k += 4) {
            a0 = fmaf(sh_t[kb + k + 0][r], Wp[(kb + k + 0) * 5 + j], a0);
            a1 = fmaf(sh_t[kb + k + 1][r], Wp[(kb + k + 1) * 5 + j], a1);
            a2 = fmaf(sh_t[kb + k + 2][r], Wp[(kb + k + 2) * 5 + j], a2);
            a3 = fmaf(sh_t[kb + k + 3][r], Wp[(kb + k + 3) * 5 + j], a3);
        }
        u.r.predred[tid] = (a0 + a1) + (a2 + a3);
    }
    __syncthreads();

    // ---- final combine + store (first 256 threads handle 256 float4s) ----
    if (tid < EPB * 16) {
        const int rr = tid >> 4;
        const int c4 = (tid & 15) * 4;
        float4 s = make_float4(0.f, 0.f, 0.f, 0.f);
        #pragma unroll
        for (int q = 0; q < 8; q++) {
            float4 p = *(const float4*)&u.r.red[q][rr][c4];
            s.x += p.x; s.y += p.y; s.z += p.z; s.w += p.w;
        }
        float4 bbv = *(const float4*)&be[c4];
        const int ebase = side ? (BATCH * 64) : 0;
        *(float4*)&out[ebase + (row0 + rr) * 64 + c4] =
            make_float4(s.x + bbv.x, s.y + bbv.y, s.z + bbv.z, s.w + bbv.w);
    }
    if (tid < EPB * 5) {
        int r = tid / 5, j = tid - r * 5;
        float v = u.r.predred[r * 10 + j] + u.r.predred[r * 10 + 5 + j] + bp[j];
        const int pbase = BATCH * 128 + (side ? BATCH * 5 : 0);
        out[pbase + (row0 + r) * 5 + j] = v;
    }
}

// ============================================================================
extern "C" void kernel_launch(void* const* d_in, const int* in_sizes, int n_in,
                              void* d_out, int out_size)
{
    const unsigned int* s_words = (const unsigned int*)d_in[0];
    const float* x        = (const float*)d_in[1];
    const float* W_bow_h  = (const float*)d_in[2];
    const float* b_bow_h  = (const float*)d_in[3];
    const float* W_bow_p  = (const float*)d_in[4];
    const float* b_bow_p  = (const float*)d_in[5];
    const float* W_bow_e  = (const float*)d_in[6];
    const float* b_bow_e  = (const float*)d_in[7];
    const float* W_beo_h  = (const float*)d_in[8];
    const float* b_beo_h  = (const float*)d_in[9];
    const float* W_beo_p  = (const float*)d_in[10];
    const float* b_beo_p  = (const float*)d_in[11];
    const float* W_beo_e  = (const float*)d_in[12];
    const float* b_beo_e  = (const float*)d_in[13];
    float* out = (float*)d_out;

    fused_hidden_kernel<<<K2_BLOCKS + K1_BLOCKS, 256>>>(
        s_words, W_bow_h, b_bow_h, x, W_beo_h, b_beo_h);

    dim3 g3(BATCH / EPB, 2);
    epilogue_kernel<<<g3, 512>>>(W_bow_e, b_bow_e, W_bow_p, b_bow_p,
                                 W_beo_e, b_beo_e, W_beo_p, b_beo_p, out);
}